// round 5
// baseline (speedup 1.0000x reference)
#include <cuda_runtime.h>
#include <cstdint>
#include <cstddef>

#define KDIM 512
#define NRE 257
#define NTOT 514
#define BM 256
#define BN 64
#define BK 32
#define STAGES 3
#define THREADS 256
#define A_STAGE_BYTES (BM * BK * 4)          // 32768
#define B_OFF (STAGES * A_STAGE_BYTES)       // 98304
#define B_BYTES (BN * KDIM * 4)              // 131072
#define SMEM_BYTES (B_OFF + B_BYTES)         // 229376
#define STG_STRIDE 68                        // epilogue staging row stride (floats)

__device__ __forceinline__ void mma_tf32(float& c0, float& c1, float& c2, float& c3,
                                         uint32_t a0, uint32_t a1, uint32_t a2, uint32_t a3,
                                         uint32_t b0, uint32_t b1) {
    asm volatile(
        "mma.sync.aligned.m16n8k8.row.col.f32.tf32.tf32.f32 "
        "{%0,%1,%2,%3}, {%4,%5,%6,%7}, {%8,%9}, {%0,%1,%2,%3};\n"
        : "+f"(c0), "+f"(c1), "+f"(c2), "+f"(c3)
        : "r"(a0), "r"(a1), "r"(a2), "r"(a3), "r"(b0), "r"(b1));
}

__device__ __forceinline__ uint32_t f2tf32(float f) {
    uint32_t r;
    asm volatile("cvt.rna.tf32.f32 %0, %1;\n" : "=r"(r) : "f"(f));
    return r;
}

__device__ __forceinline__ uint32_t f2tf32_u(uint32_t fbits) {
    uint32_t r;
    asm volatile("cvt.rna.tf32.f32 %0, %1;\n" : "=r"(r) : "r"(fbits));
    return r;
}

__device__ __forceinline__ void cpa16(uint32_t dst, const float* src) {
    asm volatile("cp.async.cg.shared.global [%0], [%1], 16;" :: "r"(dst), "l"(src));
}

template <int N>
__device__ __forceinline__ void cpa_wait() {
    asm volatile("cp.async.wait_group %0;" :: "n"(N) : "memory");
}

// Cooperative A tile load: all 256 threads load the full 256x32 stage (2048 x 16B).
__device__ __forceinline__ void load_A(const float* __restrict__ X, uint32_t smem_u32,
                                       int m0, int tid, int kt, int stage) {
    const uint32_t sbase = smem_u32 + stage * A_STAGE_BYTES;
#pragma unroll
    for (int i = 0; i < 8; i++) {
        int idx = tid + i * THREADS;      // 0..2047
        int row = idx >> 3;               // 0..255
        int ch  = idx & 7;                // 16B chunk
        uint32_t dst = sbase + row * 128 + ((ch * 16) ^ ((row & 7) * 16));
        cpa16(dst, X + (size_t)(m0 + row) * KDIM + kt * BK + ch * 4);
    }
    asm volatile("cp.async.commit_group;" ::: "memory");
}

__global__ void __launch_bounds__(THREADS, 1)
rfft_wmma_kernel(const float* __restrict__ X, const float* __restrict__ MR,
                 const float* __restrict__ MI, float* __restrict__ OUT, int M) {
    extern __shared__ __align__(1024) char smem[];
    uint32_t* Asm = (uint32_t*)smem;                  // raw fp32 bits, swizzled
    uint32_t* Bsm = (uint32_t*)(smem + B_OFF);        // tf32(rna) bits, swizzled, persistent

    const int tid = threadIdx.x;
    const int w = tid >> 5;
    const int lane = tid & 31;
    const int wm = w >> 1;            // 0..3 : 64-row slice of M
    const int wn = w & 1;             // 0..1 : 32-col slice of N
    const int g = lane >> 2;          // 0..7
    const int t = lane & 3;           // 0..3
    const int m0 = blockIdx.y * BM;
    const int n0 = blockIdx.x * BN;
    const uint32_t smem_u32 = (uint32_t)__cvta_generic_to_shared(smem);

    // ---- prologue: start cooperative A pipeline ----
#pragma unroll
    for (int p = 0; p < STAGES; p++)
        load_A(X, smem_u32, m0, tid, p, p);

    // ---- prologue: cooperative B load + one-time rna tf32 conversion ----
    // B[64 n-rows][512 k] persistent; swizzled in 16B units: chunk' = c4 ^ (n&7)
    {
#pragma unroll
        for (int i = 0; i < 32; i++) {
            int cid = tid + i * THREADS;      // 0..8191
            int nl = cid >> 7;                // 0..63
            int c4 = cid & 127;               // float4 chunk within row
            int ng = n0 + nl;
            float4 v = make_float4(0.f, 0.f, 0.f, 0.f);
            if (ng < NRE)
                v = *(const float4*)(MR + (size_t)ng * KDIM + c4 * 4);
            else if (ng < NTOT)
                v = *(const float4*)(MI + (size_t)(ng - NRE) * KDIM + c4 * 4);
            uint4 o;
            o.x = f2tf32(v.x); o.y = f2tf32(v.y);
            o.z = f2tf32(v.z); o.w = f2tf32(v.w);
            ((uint4*)Bsm)[nl * 128 + (c4 ^ (nl & 7))] = o;
        }
    }

    float acc[4][4][4];
#pragma unroll
    for (int mb = 0; mb < 4; mb++)
#pragma unroll
        for (int nb = 0; nb < 4; nb++)
#pragma unroll
            for (int j = 0; j < 4; j++)
                acc[mb][nb][j] = 0.f;

    const int gsw = g << 2;   // swizzle XOR (row&7 == g for all fragment rows)

    const uint32_t* aRow[4];
#pragma unroll
    for (int mb = 0; mb < 4; mb++)
        aRow[mb] = Asm + (wm * 64 + mb * 16 + g) * 32;
    const uint32_t* bRow[4];
#pragma unroll
    for (int nb = 0; nb < 4; nb++)
        bRow[nb] = Bsm + (wn * 32 + nb * 8 + g) * KDIM;

    // ---- mainloop: CTA-synchronized 3-stage pipeline ----
#pragma unroll 1
    for (int kt = 0; kt < KDIM / BK; kt++) {
        if (kt < 14)       cpa_wait<2>();
        else if (kt == 14) cpa_wait<1>();
        else               cpa_wait<0>();
        __syncthreads();   // stage kt%3 (and B on kt=0) visible to all warps

        const int sOff = (kt % STAGES) * (A_STAGE_BYTES / 4);
#pragma unroll
        for (int ks = 0; ks < 4; ks++) {
            const int kb = ks * 8;
            uint32_t a[4][4], b[4][2];
#pragma unroll
            for (int mb = 0; mb < 4; mb++) {
                const uint32_t* ap = aRow[mb] + sOff;
                const int c0 = (kb + t) ^ gsw;
                const int c1 = (kb + t + 4) ^ gsw;
                a[mb][0] = f2tf32_u(ap[c0]);
                a[mb][1] = f2tf32_u(ap[c0 + 256]);    // row + 8
                a[mb][2] = f2tf32_u(ap[c1]);
                a[mb][3] = f2tf32_u(ap[c1 + 256]);
            }
            const int kg = kt * BK + kb + t;
#pragma unroll
            for (int nb = 0; nb < 4; nb++) {
                b[nb][0] = bRow[nb][kg ^ gsw];
                b[nb][1] = bRow[nb][(kg + 4) ^ gsw];
            }
#pragma unroll
            for (int mb = 0; mb < 4; mb++)
#pragma unroll
                for (int nb = 0; nb < 4; nb++)
                    mma_tf32(acc[mb][nb][0], acc[mb][nb][1], acc[mb][nb][2], acc[mb][nb][3],
                             a[mb][0], a[mb][1], a[mb][2], a[mb][3],
                             b[nb][0], b[nb][1]);
        }

        __syncthreads();   // all warps done reading stage kt%3
        if (kt + STAGES < KDIM / BK)
            load_A(X, smem_u32, m0, tid, kt + STAGES, kt % STAGES);
    }

    // ---- epilogue: stage in smem (overwrites A region), coalesced stores ----
    __syncthreads();
    float* stg = (float*)smem;     // 256 rows x STG_STRIDE floats (< A region)
#pragma unroll
    for (int mb = 0; mb < 4; mb++) {
#pragma unroll
        for (int nb = 0; nb < 4; nb++) {
            const int row = wm * 64 + mb * 16 + g;
            const int col = wn * 32 + nb * 8 + 2 * t;
            stg[row * STG_STRIDE + col]           = acc[mb][nb][0];
            stg[row * STG_STRIDE + col + 1]       = acc[mb][nb][1];
            stg[(row + 8) * STG_STRIDE + col]     = acc[mb][nb][2];
            stg[(row + 8) * STG_STRIDE + col + 1] = acc[mb][nb][3];
        }
    }
    __syncthreads();

    float* re = OUT;
    float* im = OUT + (size_t)M * NRE;
#pragma unroll
    for (int rr = 0; rr < 32; rr++) {
        const int row = w * 32 + rr;
        const size_t r = m0 + row;
        const float v0 = stg[row * STG_STRIDE + lane];
        const float v1 = stg[row * STG_STRIDE + 32 + lane];
        const int na = n0 + lane;
        const int nbv = n0 + 32 + lane;
        if (na < NRE)       re[r * NRE + na] = v0;
        else if (na < NTOT) im[r * NRE + (na - NRE)] = v0;
        if (nbv < NRE)       re[r * NRE + nbv] = v1;
        else if (nbv < NTOT) im[r * NRE + (nbv - NRE)] = v1;
    }
}

extern "C" void kernel_launch(void* const* d_in, const int* in_sizes, int n_in,
                              void* d_out, int out_size) {
    const float* X  = (const float*)d_in[0];
    const float* MR = (const float*)d_in[1];
    const float* MI = (const float*)d_in[2];
    float* OUT = (float*)d_out;
    const int M = in_sizes[0] / KDIM;   // 128000

    cudaFuncSetAttribute(rfft_wmma_kernel, cudaFuncAttributeMaxDynamicSharedMemorySize, SMEM_BYTES);

    dim3 grid((NTOT + BN - 1) / BN, M / BM);   // (9, 500)
    rfft_wmma_kernel<<<grid, THREADS, SMEM_BYTES>>>(X, MR, MI, OUT, M);
}

// round 6
// speedup vs baseline: 1.1189x; 1.1189x over previous
#include <cuda_runtime.h>
#include <cstdint>
#include <cstddef>

#define KDIM 512
#define NRE 257
#define NTOT 514
#define BM 256
#define BN 64
#define BK 32
#define STAGES 3
#define THREADS 512
#define A_STAGE_BYTES (BM * BK * 4)          // 32768
#define B_OFF (STAGES * A_STAGE_BYTES)       // 98304
#define B_BYTES (BN * KDIM * 4)              // 131072
#define SMEM_BYTES (B_OFF + B_BYTES)         // 229376
#define STG_STRIDE 68                        // epilogue staging row stride (floats)

__device__ __forceinline__ void mma_tf32(float& c0, float& c1, float& c2, float& c3,
                                         uint32_t a0, uint32_t a1, uint32_t a2, uint32_t a3,
                                         uint32_t b0, uint32_t b1) {
    asm volatile(
        "mma.sync.aligned.m16n8k8.row.col.f32.tf32.tf32.f32 "
        "{%0,%1,%2,%3}, {%4,%5,%6,%7}, {%8,%9}, {%0,%1,%2,%3};\n"
        : "+f"(c0), "+f"(c1), "+f"(c2), "+f"(c3)
        : "r"(a0), "r"(a1), "r"(a2), "r"(a3), "r"(b0), "r"(b1));
}

__device__ __forceinline__ uint32_t f2tf32(float f) {
    uint32_t r;
    asm volatile("cvt.rna.tf32.f32 %0, %1;\n" : "=r"(r) : "f"(f));
    return r;
}

__device__ __forceinline__ uint32_t f2tf32_u(uint32_t fbits) {
    uint32_t r;
    asm volatile("cvt.rna.tf32.f32 %0, %1;\n" : "=r"(r) : "r"(fbits));
    return r;
}

__device__ __forceinline__ void cpa16(uint32_t dst, const float* src) {
    asm volatile("cp.async.cg.shared.global [%0], [%1], 16;" :: "r"(dst), "l"(src));
}

template <int N>
__device__ __forceinline__ void cpa_wait() {
    asm volatile("cp.async.wait_group %0;" :: "n"(N) : "memory");
}

// Cooperative A tile load: 512 threads load the full 256x32 stage (2048 x 16B).
__device__ __forceinline__ void load_A(const float* __restrict__ X, uint32_t smem_u32,
                                       int m0, int tid, int kt, int stage) {
    const uint32_t sbase = smem_u32 + stage * A_STAGE_BYTES;
#pragma unroll
    for (int i = 0; i < 4; i++) {
        int idx = tid + i * THREADS;      // 0..2047
        int row = idx >> 3;               // 0..255
        int ch  = idx & 7;                // 16B chunk
        uint32_t dst = sbase + row * 128 + ((ch * 16) ^ ((row & 7) * 16));
        cpa16(dst, X + (size_t)(m0 + row) * KDIM + kt * BK + ch * 4);
    }
    asm volatile("cp.async.commit_group;" ::: "memory");
}

__global__ void __launch_bounds__(THREADS, 1)
rfft_wmma_kernel(const float* __restrict__ X, const float* __restrict__ MR,
                 const float* __restrict__ MI, float* __restrict__ OUT, int M) {
    extern __shared__ __align__(1024) char smem[];
    uint32_t* Asm = (uint32_t*)smem;                  // raw fp32 bits, swizzled
    uint32_t* Bsm = (uint32_t*)(smem + B_OFF);        // tf32(rna) bits, swizzled, persistent

    const int tid = threadIdx.x;
    const int w = tid >> 5;
    const int lane = tid & 31;
    const int wm = w >> 1;            // 0..7 : 32-row slice of M
    const int wn = w & 1;             // 0..1 : 32-col slice of N
    const int g = lane >> 2;          // 0..7
    const int t = lane & 3;           // 0..3
    const int m0 = blockIdx.y * BM;
    const int n0 = blockIdx.x * BN;
    const uint32_t smem_u32 = (uint32_t)__cvta_generic_to_shared(smem);

    // ---- prologue: start cooperative A pipeline ----
#pragma unroll
    for (int p = 0; p < STAGES; p++)
        load_A(X, smem_u32, m0, tid, p, p);

    // ---- prologue: cooperative B load + one-time rna tf32 conversion ----
    // B[64 n-rows][512 k] persistent; swizzled in 16B units: chunk' = c4 ^ (n&7)
    {
#pragma unroll
        for (int i = 0; i < 16; i++) {
            int cid = tid + i * THREADS;      // 0..8191
            int nl = cid >> 7;                // 0..63
            int c4 = cid & 127;               // float4 chunk within row
            int ng = n0 + nl;
            float4 v = make_float4(0.f, 0.f, 0.f, 0.f);
            if (ng < NRE)
                v = *(const float4*)(MR + (size_t)ng * KDIM + c4 * 4);
            else if (ng < NTOT)
                v = *(const float4*)(MI + (size_t)(ng - NRE) * KDIM + c4 * 4);
            uint4 o;
            o.x = f2tf32(v.x); o.y = f2tf32(v.y);
            o.z = f2tf32(v.z); o.w = f2tf32(v.w);
            ((uint4*)Bsm)[nl * 128 + (c4 ^ (nl & 7))] = o;
        }
    }

    float acc[2][4][4];
#pragma unroll
    for (int mb = 0; mb < 2; mb++)
#pragma unroll
        for (int nb = 0; nb < 4; nb++)
#pragma unroll
            for (int j = 0; j < 4; j++)
                acc[mb][nb][j] = 0.f;

    const int gsw = g << 2;   // swizzle XOR (row&7 == g for all fragment rows)

    const uint32_t* aRow[2];
#pragma unroll
    for (int mb = 0; mb < 2; mb++)
        aRow[mb] = Asm + (wm * 32 + mb * 16 + g) * 32;
    const uint32_t* bRow[4];
#pragma unroll
    for (int nb = 0; nb < 4; nb++)
        bRow[nb] = Bsm + (wn * 32 + nb * 8 + g) * KDIM;

    // ---- mainloop: CTA-synchronized 3-stage pipeline ----
#pragma unroll 1
    for (int kt = 0; kt < KDIM / BK; kt++) {
        if (kt < 14)       cpa_wait<2>();
        else if (kt == 14) cpa_wait<1>();
        else               cpa_wait<0>();
        __syncthreads();   // stage kt%3 (and B on kt=0) visible to all warps

        const int sOff = (kt % STAGES) * (A_STAGE_BYTES / 4);
#pragma unroll
        for (int ks = 0; ks < 4; ks++) {
            const int kb = ks * 8;
            uint32_t a[2][4], b[4][2];
#pragma unroll
            for (int mb = 0; mb < 2; mb++) {
                const uint32_t* ap = aRow[mb] + sOff;
                const int c0 = (kb + t) ^ gsw;
                const int c1 = (kb + t + 4) ^ gsw;
                a[mb][0] = f2tf32_u(ap[c0]);
                a[mb][1] = f2tf32_u(ap[c0 + 256]);    // row + 8
                a[mb][2] = f2tf32_u(ap[c1]);
                a[mb][3] = f2tf32_u(ap[c1 + 256]);
            }
            const int kg = kt * BK + kb + t;
#pragma unroll
            for (int nb = 0; nb < 4; nb++) {
                b[nb][0] = bRow[nb][kg ^ gsw];
                b[nb][1] = bRow[nb][(kg + 4) ^ gsw];
            }
#pragma unroll
            for (int mb = 0; mb < 2; mb++)
#pragma unroll
                for (int nb = 0; nb < 4; nb++)
                    mma_tf32(acc[mb][nb][0], acc[mb][nb][1], acc[mb][nb][2], acc[mb][nb][3],
                             a[mb][0], a[mb][1], a[mb][2], a[mb][3],
                             b[nb][0], b[nb][1]);
        }

        __syncthreads();   // all warps done reading stage kt%3
        if (kt + STAGES < KDIM / BK)
            load_A(X, smem_u32, m0, tid, kt + STAGES, kt % STAGES);
    }

    // ---- epilogue: stage in smem (overwrites A region), coalesced stores ----
    __syncthreads();
    float* stg = (float*)smem;     // 256 rows x STG_STRIDE floats (< A region)
#pragma unroll
    for (int mb = 0; mb < 2; mb++) {
#pragma unroll
        for (int nb = 0; nb < 4; nb++) {
            const int row = wm * 32 + mb * 16 + g;
            const int col = wn * 32 + nb * 8 + 2 * t;
            stg[row * STG_STRIDE + col]           = acc[mb][nb][0];
            stg[row * STG_STRIDE + col + 1]       = acc[mb][nb][1];
            stg[(row + 8) * STG_STRIDE + col]     = acc[mb][nb][2];
            stg[(row + 8) * STG_STRIDE + col + 1] = acc[mb][nb][3];
        }
    }
    __syncthreads();

    float* re = OUT;
    float* im = OUT + (size_t)M * NRE;
#pragma unroll
    for (int rr = 0; rr < 16; rr++) {
        const int row = w * 16 + rr;
        const size_t r = m0 + row;
        const float v0 = stg[row * STG_STRIDE + lane];
        const float v1 = stg[row * STG_STRIDE + 32 + lane];
        const int na = n0 + lane;
        const int nbv = n0 + 32 + lane;
        if (na < NRE)       re[r * NRE + na] = v0;
        else if (na < NTOT) im[r * NRE + (na - NRE)] = v0;
        if (nbv < NRE)       re[r * NRE + nbv] = v1;
        else if (nbv < NTOT) im[r * NRE + (nbv - NRE)] = v1;
    }
}

extern "C" void kernel_launch(void* const* d_in, const int* in_sizes, int n_in,
                              void* d_out, int out_size) {
    const float* X  = (const float*)d_in[0];
    const float* MR = (const float*)d_in[1];
    const float* MI = (const float*)d_in[2];
    float* OUT = (float*)d_out;
    const int M = in_sizes[0] / KDIM;   // 128000

    cudaFuncSetAttribute(rfft_wmma_kernel, cudaFuncAttributeMaxDynamicSharedMemorySize, SMEM_BYTES);

    dim3 grid((NTOT + BN - 1) / BN, M / BM);   // (9, 500)
    rfft_wmma_kernel<<<grid, THREADS, SMEM_BYTES>>>(X, MR, MI, OUT, M);
}

// round 7
// speedup vs baseline: 1.5102x; 1.3497x over previous
#include <cuda_runtime.h>
#include <cstdint>
#include <cstddef>

#define KDIM 512
#define NRE 257
#define NTOT 514
#define NPAD 576
#define BM 128
#define BN 64
#define BK 32
#define STAGES 3
#define THREADS 256
#define A_STAGE_BYTES (BM * BK * 4)                 // 16384
#define B_STAGE_BYTES (BN * BK * 4)                 // 8192
#define STAGE_BYTES (A_STAGE_BYTES + B_STAGE_BYTES) // 24576
#define SMEM_BYTES (STAGES * STAGE_BYTES)           // 73728
#define STG_STRIDE 68

// Pre-converted, zero-padded B (tf32 bits): rows 0..256 = MR, 257..513 = MI, 514..575 = 0
__device__ uint32_t g_Bcvt[NPAD * KDIM];

__device__ __forceinline__ void mma_tf32(float& c0, float& c1, float& c2, float& c3,
                                         uint32_t a0, uint32_t a1, uint32_t a2, uint32_t a3,
                                         uint32_t b0, uint32_t b1) {
    asm volatile(
        "mma.sync.aligned.m16n8k8.row.col.f32.tf32.tf32.f32 "
        "{%0,%1,%2,%3}, {%4,%5,%6,%7}, {%8,%9}, {%0,%1,%2,%3};\n"
        : "+f"(c0), "+f"(c1), "+f"(c2), "+f"(c3)
        : "r"(a0), "r"(a1), "r"(a2), "r"(a3), "r"(b0), "r"(b1));
}

__device__ __forceinline__ uint32_t f2tf32(float f) {
    uint32_t r;
    asm volatile("cvt.rna.tf32.f32 %0, %1;\n" : "=r"(r) : "f"(f));
    return r;
}

__device__ __forceinline__ uint32_t f2tf32_u(uint32_t fbits) {
    uint32_t r;
    asm volatile("cvt.rna.tf32.f32 %0, %1;\n" : "=r"(r) : "r"(fbits));
    return r;
}

__device__ __forceinline__ void cpa16(uint32_t dst, const void* src) {
    asm volatile("cp.async.cg.shared.global [%0], [%1], 16;" :: "r"(dst), "l"(src));
}

template <int N>
__device__ __forceinline__ void cpa_wait() {
    asm volatile("cp.async.wait_group %0;" :: "n"(N) : "memory");
}

// ---- pre-kernel: build padded tf32 B matrix ----
__global__ void build_B_kernel(const float* __restrict__ MR, const float* __restrict__ MI) {
    int idx = blockIdx.x * blockDim.x + threadIdx.x;   // 0 .. NPAD*KDIM/4 - 1 (float4 units)
    int n = idx >> 7;            // row (KDIM/4 = 128 chunks per row)
    int c4 = idx & 127;
    float4 v = make_float4(0.f, 0.f, 0.f, 0.f);
    if (n < NRE)       v = *(const float4*)(MR + (size_t)n * KDIM + c4 * 4);
    else if (n < NTOT) v = *(const float4*)(MI + (size_t)(n - NRE) * KDIM + c4 * 4);
    uint4 o;
    o.x = f2tf32(v.x); o.y = f2tf32(v.y); o.z = f2tf32(v.z); o.w = f2tf32(v.w);
    ((uint4*)g_Bcvt)[idx] = o;
}

// Cooperative stage load: A 128x32 raw fp32 + B 64x32 pre-converted, both swizzled.
__device__ __forceinline__ void load_stage(const float* __restrict__ X, uint32_t smem_u32,
                                           int m0, int n0, int tid, int kt, int stage) {
    const uint32_t abase = smem_u32 + stage * STAGE_BYTES;
#pragma unroll
    for (int i = 0; i < 4; i++) {
        int idx = tid + i * THREADS;      // 0..1023
        int row = idx >> 3;               // 0..127
        int ch  = idx & 7;
        uint32_t dst = abase + row * 128 + ((ch * 16) ^ ((row & 7) * 16));
        cpa16(dst, X + (size_t)(m0 + row) * KDIM + kt * BK + ch * 4);
    }
    const uint32_t bbase = abase + A_STAGE_BYTES;
#pragma unroll
    for (int i = 0; i < 2; i++) {
        int idx = tid + i * THREADS;      // 0..511
        int row = idx >> 3;               // 0..63
        int ch  = idx & 7;
        uint32_t dst = bbase + row * 128 + ((ch * 16) ^ ((row & 7) * 16));
        cpa16(dst, g_Bcvt + (size_t)(n0 + row) * KDIM + kt * BK + ch * 4);
    }
    asm volatile("cp.async.commit_group;" ::: "memory");
}

__global__ void __launch_bounds__(THREADS, 2)
rfft_wmma_kernel(const float* __restrict__ X, float* __restrict__ OUT, int M) {
    extern __shared__ __align__(1024) char smem[];
    uint32_t* Ssm = (uint32_t*)smem;

    const int tid = threadIdx.x;
    const int w = tid >> 5;
    const int lane = tid & 31;
    const int wm = w >> 1;            // 0..3 : 32-row slice of M
    const int wn = w & 1;             // 0..1 : 32-col slice of N
    const int g = lane >> 2;
    const int t = lane & 3;
    const int m0 = blockIdx.y * BM;
    const int n0 = blockIdx.x * BN;
    const uint32_t smem_u32 = (uint32_t)__cvta_generic_to_shared(smem);

#pragma unroll
    for (int p = 0; p < STAGES; p++)
        load_stage(X, smem_u32, m0, n0, tid, p, p);

    float acc[2][4][4];
#pragma unroll
    for (int mb = 0; mb < 2; mb++)
#pragma unroll
        for (int nb = 0; nb < 4; nb++)
#pragma unroll
            for (int j = 0; j < 4; j++)
                acc[mb][nb][j] = 0.f;

    const int gsw = g << 2;

    // per-thread row offsets in 32-bit elements, within a stage
    int aOff[2], bOff[4];
#pragma unroll
    for (int mb = 0; mb < 2; mb++)
        aOff[mb] = (wm * 32 + mb * 16 + g) * 32;
#pragma unroll
    for (int nb = 0; nb < 4; nb++)
        bOff[nb] = (A_STAGE_BYTES / 4) + (wn * 32 + nb * 8 + g) * 32;

#pragma unroll 1
    for (int kt = 0; kt < KDIM / BK; kt++) {
        if (kt < 14)       cpa_wait<2>();
        else if (kt == 14) cpa_wait<1>();
        else               cpa_wait<0>();
        __syncthreads();

        const uint32_t* sp = Ssm + (kt % STAGES) * (STAGE_BYTES / 4);
#pragma unroll
        for (int ks = 0; ks < 4; ks++) {
            const int kb = ks * 8;
            const int c0 = (kb + t) ^ gsw;
            const int c1 = (kb + t + 4) ^ gsw;
            uint32_t a[2][4], b[4][2];
#pragma unroll
            for (int mb = 0; mb < 2; mb++) {
                const uint32_t* ap = sp + aOff[mb];
                a[mb][0] = f2tf32_u(ap[c0]);
                a[mb][1] = f2tf32_u(ap[c0 + 256]);   // row + 8
                a[mb][2] = f2tf32_u(ap[c1]);
                a[mb][3] = f2tf32_u(ap[c1 + 256]);
            }
#pragma unroll
            for (int nb = 0; nb < 4; nb++) {
                const uint32_t* bp = sp + bOff[nb];
                b[nb][0] = bp[c0];
                b[nb][1] = bp[c1];
            }
#pragma unroll
            for (int mb = 0; mb < 2; mb++)
#pragma unroll
                for (int nb = 0; nb < 4; nb++)
                    mma_tf32(acc[mb][nb][0], acc[mb][nb][1], acc[mb][nb][2], acc[mb][nb][3],
                             a[mb][0], a[mb][1], a[mb][2], a[mb][3],
                             b[nb][0], b[nb][1]);
        }

        __syncthreads();
        if (kt + STAGES < KDIM / BK)
            load_stage(X, smem_u32, m0, n0, tid, kt + STAGES, kt % STAGES);
    }

    // ---- epilogue: smem-staged, coalesced stores ----
    __syncthreads();
    float* stg = (float*)smem;     // 128 rows x STG_STRIDE floats (34.8 KB < 72 KB)
#pragma unroll
    for (int mb = 0; mb < 2; mb++) {
#pragma unroll
        for (int nb = 0; nb < 4; nb++) {
            const int row = wm * 32 + mb * 16 + g;
            const int col = wn * 32 + nb * 8 + 2 * t;
            stg[row * STG_STRIDE + col]           = acc[mb][nb][0];
            stg[row * STG_STRIDE + col + 1]       = acc[mb][nb][1];
            stg[(row + 8) * STG_STRIDE + col]     = acc[mb][nb][2];
            stg[(row + 8) * STG_STRIDE + col + 1] = acc[mb][nb][3];
        }
    }
    __syncthreads();

    float* re = OUT;
    float* im = OUT + (size_t)M * NRE;
#pragma unroll
    for (int rr = 0; rr < 16; rr++) {
        const int row = w * 16 + rr;
        const size_t r = m0 + row;
        const float v0 = stg[row * STG_STRIDE + lane];
        const float v1 = stg[row * STG_STRIDE + 32 + lane];
        const int na = n0 + lane;
        const int nbv = n0 + 32 + lane;
        if (na < NRE)       re[r * NRE + na] = v0;
        else if (na < NTOT) im[r * NRE + (na - NRE)] = v0;
        if (nbv < NRE)       re[r * NRE + nbv] = v1;
        else if (nbv < NTOT) im[r * NRE + (nbv - NRE)] = v1;
    }
}

extern "C" void kernel_launch(void* const* d_in, const int* in_sizes, int n_in,
                              void* d_out, int out_size) {
    const float* X  = (const float*)d_in[0];
    const float* MR = (const float*)d_in[1];
    const float* MI = (const float*)d_in[2];
    float* OUT = (float*)d_out;
    const int M = in_sizes[0] / KDIM;   // 128000

    // 1) build padded tf32 B (576*512/4 float4 elements)
    build_B_kernel<<<(NPAD * KDIM / 4) / 256, 256>>>(MR, MI);

    // 2) GEMM
    cudaFuncSetAttribute(rfft_wmma_kernel, cudaFuncAttributeMaxDynamicSharedMemorySize, SMEM_BYTES);
    dim3 grid(NPAD / BN, M / BM);   // (9, 1000)
    rfft_wmma_kernel<<<grid, THREADS, SMEM_BYTES>>>(X, OUT, M);
}

// round 8
// speedup vs baseline: 1.7430x; 1.1542x over previous
#include <cuda_runtime.h>
#include <cstdint>
#include <cstddef>

#define KDIM 512
#define NRE 257
#define NTOT 514
#define NPAD 576
#define BM 128
#define BN 96
#define BK 32
#define STAGES 3
#define THREADS 256
#define A_STAGE_BYTES (BM * BK * 4)                 // 16384
#define B_STAGE_BYTES (BN * BK * 4)                 // 12288
#define STAGE_BYTES (A_STAGE_BYTES + B_STAGE_BYTES) // 28672
#define SMEM_BYTES (STAGES * STAGE_BYTES)           // 86016
#define B_OFF32 (A_STAGE_BYTES / 4)                 // 4096
#define STG_STRIDE 100

// Pre-converted, zero-padded, k-pair-permuted B (tf32 bits).
// Row n, group kg: element order [k0,k4,k1,k5,k2,k6,k3,k7] so (t, t+4) is 8B-contiguous.
__device__ uint32_t g_Bcvt[NPAD * KDIM];

__device__ __forceinline__ void mma_tf32(float& c0, float& c1, float& c2, float& c3,
                                         uint32_t a0, uint32_t a1, uint32_t a2, uint32_t a3,
                                         uint32_t b0, uint32_t b1) {
    asm volatile(
        "mma.sync.aligned.m16n8k8.row.col.f32.tf32.tf32.f32 "
        "{%0,%1,%2,%3}, {%4,%5,%6,%7}, {%8,%9}, {%0,%1,%2,%3};\n"
        : "+f"(c0), "+f"(c1), "+f"(c2), "+f"(c3)
        : "r"(a0), "r"(a1), "r"(a2), "r"(a3), "r"(b0), "r"(b1));
}

__device__ __forceinline__ uint32_t f2tf32(float f) {
    uint32_t r;
    asm volatile("cvt.rna.tf32.f32 %0, %1;\n" : "=r"(r) : "f"(f));
    return r;
}

__device__ __forceinline__ uint32_t f2tf32_u(uint32_t fbits) {
    uint32_t r;
    asm volatile("cvt.rna.tf32.f32 %0, %1;\n" : "=r"(r) : "r"(fbits));
    return r;
}

__device__ __forceinline__ void cpa16(uint32_t dst, const void* src) {
    asm volatile("cp.async.cg.shared.global [%0], [%1], 16;" :: "r"(dst), "l"(src));
}

template <int N>
__device__ __forceinline__ void cpa_wait() {
    asm volatile("cp.async.wait_group %0;" :: "n"(N) : "memory");
}

// ---- pre-kernel: padded, permuted tf32 B ----
__global__ void build_B_kernel(const float* __restrict__ MR, const float* __restrict__ MI) {
    int idx = blockIdx.x * blockDim.x + threadIdx.x;   // 0 .. NPAD*KDIM-1
    int n = idx >> 9;
    int k = idx & 511;
    float v = 0.f;
    if (n < NRE)       v = MR[(size_t)n * KDIM + k];
    else if (n < NTOT) v = MI[(size_t)(n - NRE) * KDIM + k];
    int p = (k & ~7) | (((k & 3) << 1) | ((k >> 2) & 1));   // pair-permute within k8 group
    g_Bcvt[(size_t)n * KDIM + p] = f2tf32(v);
}

// Cooperative stage load.
__device__ __forceinline__ void load_stage(const float* __restrict__ X, uint32_t smem_u32,
                                           int m0, int n0, int tid, int kt, int stage) {
    const uint32_t abase = smem_u32 + stage * STAGE_BYTES;
    // A: 128 rows x 32 fp32, 16B-chunk swizzle ch ^ (row&7)
#pragma unroll
    for (int i = 0; i < 4; i++) {
        int idx = tid + i * THREADS;      // 0..1023
        int row = idx >> 3;               // 0..127
        int ch  = idx & 7;
        uint32_t dst = abase + row * 128 + ((ch * 16) ^ ((row & 7) * 16));
        cpa16(dst, X + (size_t)(m0 + row) * KDIM + kt * BK + ch * 4);
    }
    // B: 96 rows x 32 tf32 (pre-permuted), 32B-window rotation by row for LDS.64
    const uint32_t bbase = abase + A_STAGE_BYTES;
#pragma unroll
    for (int i = 0; i < 3; i++) {
        int idx = tid + i * THREADS;      // 0..767
        int row = idx >> 3;               // 0..95
        int ch  = idx & 7;
        int win = ch >> 1, half = ch & 1;
        uint32_t dst = bbase + row * 128 + (((win + row) & 3) << 5) + (half << 4);
        cpa16(dst, g_Bcvt + (size_t)(n0 + row) * KDIM + kt * BK + ch * 4);
    }
    asm volatile("cp.async.commit_group;" ::: "memory");
}

__global__ void __launch_bounds__(THREADS, 2)
rfft_wmma_kernel(const float* __restrict__ X, float* __restrict__ OUT, int M) {
    extern __shared__ __align__(1024) char smem[];
    uint32_t* Ssm = (uint32_t*)smem;

    const int tid = threadIdx.x;
    const int w = tid >> 5;
    const int lane = tid & 31;
    const int wm = w >> 1;            // 0..3 : 32-row M slice
    const int wn = w & 1;             // 0..1 : 48-col N slice
    const int g = lane >> 2;          // 0..7
    const int t = lane & 3;           // 0..3
    const int m0 = blockIdx.y * BM;
    const int n0 = blockIdx.x * BN;
    const uint32_t smem_u32 = (uint32_t)__cvta_generic_to_shared(smem);

#pragma unroll
    for (int p = 0; p < STAGES; p++)
        load_stage(X, smem_u32, m0, n0, tid, p, p);

    float acc[2][6][4];
#pragma unroll
    for (int mb = 0; mb < 2; mb++)
#pragma unroll
        for (int nb = 0; nb < 6; nb++)
#pragma unroll
            for (int j = 0; j < 4; j++)
                acc[mb][nb][j] = 0.f;

    const int gsw = g << 2;

    int aOff[2];
#pragma unroll
    for (int mb = 0; mb < 2; mb++)
        aOff[mb] = (wm * 32 + mb * 16 + g) * 32;
    int bBase[6], bRot[6];
#pragma unroll
    for (int nb = 0; nb < 6; nb++) {
        int n = wn * 48 + nb * 8 + g;
        bBase[nb] = B_OFF32 + n * 32 + t * 2;
        bRot[nb]  = n & 3;
    }

#pragma unroll 1
    for (int kt = 0; kt < KDIM / BK; kt++) {
        if (kt < 14)       cpa_wait<2>();
        else if (kt == 14) cpa_wait<1>();
        else               cpa_wait<0>();
        __syncthreads();

        const uint32_t* sp = Ssm + (kt % STAGES) * (STAGE_BYTES / 4);
#pragma unroll
        for (int ks = 0; ks < 4; ks++) {
            const int kb = ks * 8;
            const int c0 = (kb + t) ^ gsw;
            const int c1 = c0 ^ 4;
            uint32_t a[2][4];
#pragma unroll
            for (int mb = 0; mb < 2; mb++) {
                const uint32_t* ap = sp + aOff[mb];
                a[mb][0] = f2tf32_u(ap[c0]);
                a[mb][1] = f2tf32_u(ap[c0 + 256]);   // row + 8
                a[mb][2] = f2tf32_u(ap[c1]);
                a[mb][3] = f2tf32_u(ap[c1 + 256]);
            }
            uint32_t b[6][2];
#pragma unroll
            for (int nb = 0; nb < 6; nb++) {
                uint2 v = *(const uint2*)(sp + bBase[nb] + (((ks + bRot[nb]) & 3) << 3));
                b[nb][0] = v.x;
                b[nb][1] = v.y;
            }
#pragma unroll
            for (int mb = 0; mb < 2; mb++)
#pragma unroll
                for (int nb = 0; nb < 6; nb++)
                    mma_tf32(acc[mb][nb][0], acc[mb][nb][1], acc[mb][nb][2], acc[mb][nb][3],
                             a[mb][0], a[mb][1], a[mb][2], a[mb][3],
                             b[nb][0], b[nb][1]);
        }

        __syncthreads();
        if (kt + STAGES < KDIM / BK)
            load_stage(X, smem_u32, m0, n0, tid, kt + STAGES, kt % STAGES);
    }

    // ---- epilogue: smem-staged, coalesced stores ----
    __syncthreads();
    float* stg = (float*)smem;     // 128 x STG_STRIDE floats = 51.2 KB < 84 KB
#pragma unroll
    for (int mb = 0; mb < 2; mb++) {
#pragma unroll
        for (int nb = 0; nb < 6; nb++) {
            const int row = wm * 32 + mb * 16 + g;
            const int col = wn * 48 + nb * 8 + 2 * t;
            stg[row * STG_STRIDE + col]           = acc[mb][nb][0];
            stg[row * STG_STRIDE + col + 1]       = acc[mb][nb][1];
            stg[(row + 8) * STG_STRIDE + col]     = acc[mb][nb][2];
            stg[(row + 8) * STG_STRIDE + col + 1] = acc[mb][nb][3];
        }
    }
    __syncthreads();

    float* re = OUT;
    float* im = OUT + (size_t)M * NRE;
#pragma unroll
    for (int rr = 0; rr < 16; rr++) {
        const int row = w * 16 + rr;
        const size_t r = m0 + row;
#pragma unroll
        for (int c = 0; c < 3; c++) {
            const int n = n0 + c * 32 + lane;
            const float v = stg[row * STG_STRIDE + c * 32 + lane];
            if (n < NRE)       re[r * NRE + n] = v;
            else if (n < NTOT) im[r * NRE + (n - NRE)] = v;
        }
    }
}

extern "C" void kernel_launch(void* const* d_in, const int* in_sizes, int n_in,
                              void* d_out, int out_size) {
    const float* X  = (const float*)d_in[0];
    const float* MR = (const float*)d_in[1];
    const float* MI = (const float*)d_in[2];
    float* OUT = (float*)d_out;
    const int M = in_sizes[0] / KDIM;   // 128000

    build_B_kernel<<<(NPAD * KDIM) / 256, 256>>>(MR, MI);

    cudaFuncSetAttribute(rfft_wmma_kernel, cudaFuncAttributeMaxDynamicSharedMemorySize, SMEM_BYTES);
    dim3 grid(NPAD / BN, M / BM);   // (6, 1000)
    rfft_wmma_kernel<<<grid, THREADS, SMEM_BYTES>>>(X, OUT, M);
}